// round 16
// baseline (speedup 1.0000x reference)
#include <cuda_runtime.h>
#include <cuda_fp16.h>
#include <cstdint>

// ---------------------------------------------------------------------------
// Problem constants (fixed shapes)
// ---------------------------------------------------------------------------
#define T_STEPS 32
#define BATCH   128
#define DIN     2048
#define DOUT    2048
#define M_ROWS  (T_STEPS * BATCH)   // 4096

#define NCHUNKS16   (DIN / 16)      // 128 k16 chunks total
#define SPLITK      2
#define NC32_UNIT   (DIN / 32 / SPLITK)   // 32 chunk32s per work unit
#define GEMM_THREADS 256            // 8 warps; 2 CTAs/SM -> 4 warps/SMSP
#define STAGE_BYTES 24576           // Ah 8K | Al 8K | Bh 4K | Bl 4K (k=32, N=64)
#define NSTAGES 3
#define SMEM_BYTES (NSTAGES * STAGE_BYTES)   // 72 KB dynamic (x2 CTAs = 144 KB/SM)
#define ACC_W32 4                   // flush window every 4 chunk32s (K=128)

// stage region offsets
#define OFF_AH 0
#define OFF_AL 8192
#define OFF_BH 16384
#define OFF_BL 20480

// ---------------------------------------------------------------------------
// Device scratch
// ---------------------------------------------------------------------------
__device__ float g_X0[(size_t)M_ROWS * DOUT];
__device__ float g_X1[(size_t)M_ROWS * DOUT];
__device__ uint4 g_Ah[(size_t)M_ROWS * DIN / 8];
__device__ uint4 g_Al[(size_t)M_ROWS * DIN / 8];
__device__ uint4 g_Wh[(size_t)DOUT * DIN / 8];
__device__ uint4 g_Wl[(size_t)DOUT * DIN / 8];

// ---------------------------------------------------------------------------
// Helpers
// ---------------------------------------------------------------------------
__device__ __forceinline__ uint32_t smem_u32(const void* p) {
    uint32_t a;
    asm("{ .reg .u64 t; cvta.to.shared.u64 t, %1; cvt.u32.u64 %0, t; }"
        : "=r"(a) : "l"(p));
    return a;
}

__device__ __forceinline__ void cp16(uint32_t sm, const void* gp) {
    asm volatile("cp.async.cg.shared.global [%0], [%1], 16;"
                 :: "r"(sm), "l"(gp) : "memory");
}

__device__ __forceinline__ uint32_t pack2(float x, float y) {
    __half2 h = __floats2half2_rn(x, y);
    return *reinterpret_cast<uint32_t*>(&h);
}

__device__ __forceinline__ void mma16(float* c, const uint32_t* a,
                                      const uint32_t* b) {
    asm volatile(
        "mma.sync.aligned.m16n8k16.row.col.f32.f16.f16.f32 "
        "{%0,%1,%2,%3}, {%4,%5,%6,%7}, {%8,%9}, {%0,%1,%2,%3};"
        : "+f"(c[0]), "+f"(c[1]), "+f"(c[2]), "+f"(c[3])
        : "r"(a[0]), "r"(a[1]), "r"(a[2]), "r"(a[3]), "r"(b[0]), "r"(b[1]));
}

// split one 8-value fragment quad into hi/lo uint4s
__device__ __forceinline__ void split8(const float* v, uint4& hq, uint4& lq) {
    float h[8], l[8];
#pragma unroll
    for (int i = 0; i < 8; ++i) {
        h[i] = __half2float(__float2half_rn(v[i]));
        l[i] = v[i] - h[i];
    }
    hq = make_uint4(pack2(h[0], h[1]), pack2(h[2], h[3]),
                    pack2(h[4], h[5]), pack2(h[6], h[7]));
    lq = make_uint4(pack2(l[0], l[1]), pack2(l[2], l[3]),
                    pack2(l[4], l[5]), pack2(l[6], l[7]));
}

// ---------------------------------------------------------------------------
// Merged split+permute kernel v2: coalesced float4 loads, each thread
// produces TWO adjacent fragments (tig pair).
// Blocks [0, 2048): A path (524288 work items)
// Blocks [2048, 3072): B path (262144 work items)
// Fragment layouts identical to rounds 6-15.
// ---------------------------------------------------------------------------
__global__ void split_kernel(const float* __restrict__ A,
                             const float* __restrict__ W,
                             uint4* __restrict__ Ahid, uint4* __restrict__ Alod,
                             uint4* __restrict__ Whid, uint4* __restrict__ Wlod) {
    if (blockIdx.x < 2048) {
        const int q = blockIdx.x * blockDim.x + threadIdx.x;   // 2^19
        const int tp    = q & 1;           // tig pair: tig = 2tp, 2tp+1
        const int g     = (q >> 1) & 7;    // fragment row 0..7
        const int mtg   = (q >> 4) & 7;
        const int chunk = (q >> 7) & (NCHUNKS16 - 1);
        const int mblk  = q >> 14;

        const int m0 = mblk * 128 + mtg * 16;
        const int c0 = chunk * 16 + tp * 4;

        const float4 f0 = *(const float4*)(A + (size_t)(m0 + g) * DIN + c0);
        const float4 f1 = *(const float4*)(A + (size_t)(m0 + g + 8) * DIN + c0);
        const float4 f2 = *(const float4*)(A + (size_t)(m0 + g) * DIN + c0 + 8);
        const float4 f3 = *(const float4*)(A + (size_t)(m0 + g + 8) * DIN + c0 + 8);

        // A fragment ordering: {r0 k0,k0+1, r1 k0,k0+1, r0 k0+8,k0+9, r1 k0+8,k0+9}
        const float v0[8] = { f0.x, f0.y, f1.x, f1.y, f2.x, f2.y, f3.x, f3.y };
        const float v1[8] = { f0.z, f0.w, f1.z, f1.w, f2.z, f2.w, f3.z, f3.w };

        uint4 h0, l0, h1, l1;
        split8(v0, h0, l0);
        split8(v1, h1, l1);

        const size_t base = ((size_t)mblk * NCHUNKS16 + chunk) * 256
                          + mtg * 32 + g * 4 + tp * 2;
        Ahid[base] = h0; Ahid[base + 1] = h1;
        Alod[base] = l0; Alod[base + 1] = l1;
    } else {
        const int q = (blockIdx.x - 2048) * blockDim.x + threadIdx.x;  // 2^18
        const int tp    = q & 1;
        const int g     = (q >> 1) & 7;    // n-col within tile 0..7
        const int p     = (q >> 4) & 7;
        const int chunk = (q >> 7) & (NCHUNKS16 - 1);
        const int nblk  = q >> 14;

        const int n_a = nblk * 128 + p * 16 + g;
        const int n_b = n_a + 8;
        const int c0 = chunk * 16 + tp * 4;

        const float4 fa  = *(const float4*)(W + (size_t)n_a * DIN + c0);
        const float4 fa2 = *(const float4*)(W + (size_t)n_a * DIN + c0 + 8);
        const float4 fb  = *(const float4*)(W + (size_t)n_b * DIN + c0);
        const float4 fb2 = *(const float4*)(W + (size_t)n_b * DIN + c0 + 8);

        // B fragment ordering: {na k0,k0+1, na k0+8,k0+9, nb k0,k0+1, nb k0+8,k0+9}
        const float v0[8] = { fa.x, fa.y, fa2.x, fa2.y, fb.x, fb.y, fb2.x, fb2.y };
        const float v1[8] = { fa.z, fa.w, fa2.z, fa2.w, fb.z, fb.w, fb2.z, fb2.w };

        uint4 h0, l0, h1, l1;
        split8(v0, h0, l0);
        split8(v1, h1, l1);

        const size_t base = ((size_t)nblk * NCHUNKS16 + chunk) * 256
                          + p * 32 + g * 4 + tp * 2;
        Whid[base] = h0; Whid[base + 1] = h1;
        Wlod[base] = l0; Wlod[base + 1] = l1;
    }
}

// ---------------------------------------------------------------------------
// fp16x3 GEMM, split-K=2, CTA tile 128x64, 8 warps (warp tile 64x16),
// 2 CTAs/SM (round-11/15 proven config, byte-identical):
//   Xz[m,n] = sum_{k in half z} A[m,k] * W[n,k]
// chunk32 mainloop, 3-stage cp.async pipeline.
// Windowed two-level accumulation (RZ chain bounded to K=128, RN flush).
// ---------------------------------------------------------------------------
__global__ __launch_bounds__(GEMM_THREADS, 2)
void gemm_fp16x3_kernel(const uint4* __restrict__ Ah, const uint4* __restrict__ Al,
                        const uint4* __restrict__ Bh, const uint4* __restrict__ Bl,
                        float* __restrict__ X0, float* __restrict__ X1)
{
    extern __shared__ __align__(16) char smem[];   // NSTAGES * STAGE_BYTES

    const int tid  = threadIdx.x;
    const int wid  = tid >> 5;
    const int lane = tid & 31;
    const int bx = blockIdx.x;          // N block (0..31), 64 cols each
    const int by = blockIdx.y;          // M block (0..31)
    const int bz = blockIdx.z;          // K half (0..1)
    const int wr = wid >> 2;            // warp row (0..1)  -> 64 M-rows
    const int wc = wid & 3;             // warp col (0..3)  -> 16 N-cols

    const uint32_t sbase = smem_u32(smem);
    const int c16base = bz * (NCHUNKS16 / SPLITK);   // 0 or 64
    const int nblk = bx >> 1;           // 128-wide B layout block
    const int nhalf = bx & 1;           // which 64-slice of it

    // one stage = one chunk32: A 1024 uint4, B 512 uint4. 6 cp.async/thread.
    auto issue = [&](int c32, int s) {
        const uint32_t sb = sbase + (uint32_t)s * STAGE_BYTES;
        const size_t a0 = ((size_t)by * NCHUNKS16 + c16base + c32 * 2) * 256;
        const size_t b0 = ((size_t)nblk * NCHUNKS16 + c16base + c32 * 2) * 256
                        + (size_t)nhalf * 128;
#pragma unroll
        for (int j = 0; j < 2; ++j) {
            const int t = tid + j * 256;
            cp16(sb + OFF_AH + t * 16, Ah + a0 + t);
            cp16(sb + OFF_AL + t * 16, Al + a0 + t);
        }
        {
            const int sub = tid >> 7;          // chunk16 index 0/1
            const int off = tid & 127;
            const size_t bsrc = b0 + (size_t)sub * 256 + off;
            cp16(sb + OFF_BH + tid * 16, Bh + bsrc);
            cp16(sb + OFF_BL + tid * 16, Bl + bsrc);
        }
        asm volatile("cp.async.commit_group;" ::: "memory");
    };

    float acc[4][2][4];    // master (RN adds only)
    float macc[4][2][4];   // HMMA window accumulator
#pragma unroll
    for (int i = 0; i < 4; ++i)
#pragma unroll
        for (int j = 0; j < 2; ++j)
#pragma unroll
            for (int r = 0; r < 4; ++r) acc[i][j][r] = 0.f;

    issue(0, 0);
    issue(1, 1);

    for (int i = 0; i < NC32_UNIT; ++i) {
        asm volatile("cp.async.wait_group 1;" ::: "memory");
        __syncthreads();

        if (i + 2 < NC32_UNIT) issue(i + 2, (i + 2) % NSTAGES);
        else asm volatile("cp.async.commit_group;" ::: "memory");

        const char* st = smem + (i % NSTAGES) * STAGE_BYTES;

        if ((i & (ACC_W32 - 1)) == 0) {
#pragma unroll
            for (int mt = 0; mt < 4; ++mt)
#pragma unroll
                for (int nt = 0; nt < 2; ++nt)
#pragma unroll
                    for (int r = 0; r < 4; ++r) macc[mt][nt][r] = 0.f;
        }

#pragma unroll
        for (int s = 0; s < 2; ++s) {            // two k16 sub-chunks
            // B fragments: one n-tile pair per warp (ntg = 2wc, 2wc+1)
            uint4 bhv = *(const uint4*)(st + OFF_BH + s * 2048 + (wc * 32 + lane) * 16);
            uint4 blv = *(const uint4*)(st + OFF_BL + s * 2048 + (wc * 32 + lane) * 16);
            const uint32_t* bhp = (const uint32_t*)&bhv;   // [0,1]=nt0, [2,3]=nt1
            const uint32_t* blp = (const uint32_t*)&blv;

            // A fragments: 4 m-tiles x 2 terms
            uint4 ahv[4], alv[4];
#pragma unroll
            for (int mt = 0; mt < 4; ++mt) {
                const int mtg = wr * 4 + mt;
                ahv[mt] = *(const uint4*)(st + OFF_AH + s * 4096 + (mtg * 32 + lane) * 16);
                alv[mt] = *(const uint4*)(st + OFF_AL + s * 4096 + (mtg * 32 + lane) * 16);
            }

#pragma unroll
            for (int mt = 0; mt < 4; ++mt) {
                const uint32_t* ah = (const uint32_t*)&ahv[mt];
                const uint32_t* al = (const uint32_t*)&alv[mt];
#pragma unroll
                for (int nt = 0; nt < 2; ++nt) {
                    mma16(macc[mt][nt], ah, bhp + 2 * nt);   // hi*hi
                    mma16(macc[mt][nt], ah, blp + 2 * nt);   // hi*lo
                    mma16(macc[mt][nt], al, bhp + 2 * nt);   // lo*hi
                }
            }
        }

        if ((i & (ACC_W32 - 1)) == (ACC_W32 - 1)) {
#pragma unroll
            for (int mt = 0; mt < 4; ++mt)
#pragma unroll
                for (int nt = 0; nt < 2; ++nt)
#pragma unroll
                    for (int r = 0; r < 4; ++r) acc[mt][nt][r] += macc[mt][nt][r];
        }
    }

    // epilogue: write partial to this unit's buffer
    float* X = (bz == 0) ? X0 : X1;
    const int r = lane >> 2, c2 = (lane & 3) * 2;
#pragma unroll
    for (int mt = 0; mt < 4; ++mt) {
#pragma unroll
        for (int nt = 0; nt < 2; ++nt) {
            const int m = by * 128 + wr * 64 + mt * 16 + r;
            const int n = bx * 64 + wc * 16 + nt * 8 + c2;
            *(float2*)&X[(size_t)m * DOUT + n] =
                make_float2(acc[mt][nt][0], acc[mt][nt][1]);
            *(float2*)&X[(size_t)(m + 8) * DOUT + n] =
                make_float2(acc[mt][nt][2], acc[mt][nt][3]);
        }
    }
}

// ---------------------------------------------------------------------------
// IF-neuron scan v2: each thread runs TWO independent neuron chains
// (rows b and b+64) -> 4 independent 16B loads per t-step (2x MLP).
// Per-element math identical to rounds 14-15.
// ---------------------------------------------------------------------------
__global__ void if_scan_kernel(const float4* __restrict__ X0,
                               const float4* __restrict__ X1,
                               const float4* __restrict__ bias,
                               const float4* __restrict__ mem_init,
                               float4* __restrict__ out)
{
    const int idx = blockIdx.x * blockDim.x + threadIdx.x;   // 32768 threads
    const int o4 = idx & (DOUT / 4 - 1);   // 512 float4 per row
    const int b0 = idx >> 9;               // 0..63
    const int b1 = b0 + 64;

    const float4 bi = bias[o4];
    float4 memA = mem_init[b0 * (DOUT / 4) + o4];
    float4 memB = mem_init[b1 * (DOUT / 4) + o4];
    float4 spkA = make_float4(0.f, 0.f, 0.f, 0.f);
    float4 spkB = make_float4(0.f, 0.f, 0.f, 0.f);
    float4 accA = make_float4(0.f, 0.f, 0.f, 0.f);
    float4 accB = make_float4(0.f, 0.f, 0.f, 0.f);

#pragma unroll
    for (int t = 0; t < T_STEPS; ++t) {
        const size_t pA = ((size_t)t * BATCH + b0) * (DOUT / 4) + o4;
        const size_t pB = ((size_t)t * BATCH + b1) * (DOUT / 4) + o4;
        const float4 a0 = X0[pA], a1 = X1[pA];
        const float4 c0 = X0[pB], c1 = X1[pB];

        memA.x = memA.x * (1.f - spkA.x) + (a0.x + a1.x + bi.x);
        memA.y = memA.y * (1.f - spkA.y) + (a0.y + a1.y + bi.y);
        memA.z = memA.z * (1.f - spkA.z) + (a0.z + a1.z + bi.z);
        memA.w = memA.w * (1.f - spkA.w) + (a0.w + a1.w + bi.w);
        spkA.x = (memA.x > 1.f) ? 1.f : 0.f;
        spkA.y = (memA.y > 1.f) ? 1.f : 0.f;
        spkA.z = (memA.z > 1.f) ? 1.f : 0.f;
        spkA.w = (memA.w > 1.f) ? 1.f : 0.f;
        accA.x += spkA.x; accA.y += spkA.y; accA.z += spkA.z; accA.w += spkA.w;

        memB.x = memB.x * (1.f - spkB.x) + (c0.x + c1.x + bi.x);
        memB.y = memB.y * (1.f - spkB.y) + (c0.y + c1.y + bi.y);
        memB.z = memB.z * (1.f - spkB.z) + (c0.z + c1.z + bi.z);
        memB.w = memB.w * (1.f - spkB.w) + (c0.w + c1.w + bi.w);
        spkB.x = (memB.x > 1.f) ? 1.f : 0.f;
        spkB.y = (memB.y > 1.f) ? 1.f : 0.f;
        spkB.z = (memB.z > 1.f) ? 1.f : 0.f;
        spkB.w = (memB.w > 1.f) ? 1.f : 0.f;
        accB.x += spkB.x; accB.y += spkB.y; accB.z += spkB.z; accB.w += spkB.w;
    }
    const float inv = 1.f / (float)T_STEPS;
    out[b0 * (DOUT / 4) + o4] =
        make_float4(accA.x * inv, accA.y * inv, accA.z * inv, accA.w * inv);
    out[b1 * (DOUT / 4) + o4] =
        make_float4(accB.x * inv, accB.y * inv, accB.z * inv, accB.w * inv);
}

// ---------------------------------------------------------------------------
extern "C" void kernel_launch(void* const* d_in, const int* in_sizes, int n_in,
                              void* d_out, int out_size)
{
    const float* cur_inp  = (const float*)d_in[0];  // [T, B, DIN]
    const float* weight   = (const float*)d_in[1];  // [DOUT, DIN]
    const float* bias     = (const float*)d_in[2];  // [DOUT]
    const float* mem_init = (const float*)d_in[3];  // [B, DOUT]
    float* out = (float*)d_out;                     // [B, DOUT]

    float *X0, *X1;
    uint4 *Ah, *Al, *Wh, *Wl;
    cudaGetSymbolAddress((void**)&X0, g_X0);
    cudaGetSymbolAddress((void**)&X1, g_X1);
    cudaGetSymbolAddress((void**)&Ah, g_Ah);
    cudaGetSymbolAddress((void**)&Al, g_Al);
    cudaGetSymbolAddress((void**)&Wh, g_Wh);
    cudaGetSymbolAddress((void**)&Wl, g_Wl);

    cudaFuncSetAttribute(gemm_fp16x3_kernel,
                         cudaFuncAttributeMaxDynamicSharedMemorySize, SMEM_BYTES);

    // merged split + permute into mma fragment layout (fp16 hi/lo), v2
    split_kernel<<<3072, 256>>>(cur_inp, weight, Ah, Al, Wh, Wl);

    // fp16x3 tensor-core GEMM, split-K = 2, CTA tile 128x64, 2 CTAs/SM
    dim3 grid(DOUT / 64, M_ROWS / 128, SPLITK);   // (32, 32, 2)
    gemm_fp16x3_kernel<<<grid, GEMM_THREADS, SMEM_BYTES>>>(Ah, Al, Wh, Wl, X0, X1);

    // IF scan + split-K reduction (2 chains per thread)
    if_scan_kernel<<<256, 128>>>((const float4*)X0, (const float4*)X1,
                                 (const float4*)bias, (const float4*)mem_init,
                                 (float4*)out);
}

// round 17
// speedup vs baseline: 1.0284x; 1.0284x over previous
#include <cuda_runtime.h>
#include <cuda_fp16.h>
#include <cstdint>

// ---------------------------------------------------------------------------
// Problem constants (fixed shapes)
// ---------------------------------------------------------------------------
#define T_STEPS 32
#define BATCH   128
#define DIN     2048
#define DOUT    2048
#define M_ROWS  (T_STEPS * BATCH)   // 4096

#define NCHUNKS16   (DIN / 16)      // 128 k16 chunks total
#define SPLITK      2
#define NC32_UNIT   (DIN / 32 / SPLITK)   // 32 chunk32s per work unit
#define GEMM_THREADS 256            // 8 warps; 2 CTAs/SM -> 4 warps/SMSP
#define STAGE_BYTES 24576           // Ah 8K | Al 8K | Bh 4K | Bl 4K (k=32, N=64)
#define NSTAGES 3
#define SMEM_BYTES (NSTAGES * STAGE_BYTES)   // 72 KB dynamic (x2 CTAs = 144 KB/SM)
#define ACC_W32 4                   // flush window every 4 chunk32s (K=128)

// stage region offsets
#define OFF_AH 0
#define OFF_AL 8192
#define OFF_BH 16384
#define OFF_BL 20480

// ---------------------------------------------------------------------------
// Device scratch
// ---------------------------------------------------------------------------
__device__ float g_X0[(size_t)M_ROWS * DOUT];
__device__ float g_X1[(size_t)M_ROWS * DOUT];
__device__ uint4 g_Ah[(size_t)M_ROWS * DIN / 8];
__device__ uint4 g_Al[(size_t)M_ROWS * DIN / 8];
__device__ uint4 g_Wh[(size_t)DOUT * DIN / 8];
__device__ uint4 g_Wl[(size_t)DOUT * DIN / 8];

// ---------------------------------------------------------------------------
// Helpers
// ---------------------------------------------------------------------------
__device__ __forceinline__ uint32_t smem_u32(const void* p) {
    uint32_t a;
    asm("{ .reg .u64 t; cvta.to.shared.u64 t, %1; cvt.u32.u64 %0, t; }"
        : "=r"(a) : "l"(p));
    return a;
}

__device__ __forceinline__ void cp16(uint32_t sm, const void* gp) {
    asm volatile("cp.async.cg.shared.global [%0], [%1], 16;"
                 :: "r"(sm), "l"(gp) : "memory");
}

__device__ __forceinline__ uint32_t pack2(float x, float y) {
    __half2 h = __floats2half2_rn(x, y);
    return *reinterpret_cast<uint32_t*>(&h);
}

__device__ __forceinline__ void mma16(float* c, const uint32_t* a,
                                      const uint32_t* b) {
    asm volatile(
        "mma.sync.aligned.m16n8k16.row.col.f32.f16.f16.f32 "
        "{%0,%1,%2,%3}, {%4,%5,%6,%7}, {%8,%9}, {%0,%1,%2,%3};"
        : "+f"(c[0]), "+f"(c[1]), "+f"(c[2]), "+f"(c[3])
        : "r"(a[0]), "r"(a[1]), "r"(a[2]), "r"(a[3]), "r"(b[0]), "r"(b[1]));
}

// ---------------------------------------------------------------------------
// Merged split+permute kernel: a -> hi = fp16_rn(a), lo = fp16_rn(a - hi)
// Blocks [0, 4096): A path; blocks [4096, 6144): B path.
// Fragment layouts identical to rounds 6-11.
// ---------------------------------------------------------------------------
__global__ void split_kernel(const float* __restrict__ A,
                             const float* __restrict__ W,
                             uint4* __restrict__ Ahid, uint4* __restrict__ Alod,
                             uint4* __restrict__ Whid, uint4* __restrict__ Wlod) {
    if (blockIdx.x < 4096) {
        const int q = blockIdx.x * blockDim.x + threadIdx.x;
        const int lane  = q & 31;
        const int mtg   = (q >> 5) & 7;
        const int chunk = (q >> 8) & (NCHUNKS16 - 1);
        const int mblk  = q >> 15;

        const int g = lane >> 2, tig = lane & 3;
        const int m0 = mblk * 128 + mtg * 16;
        const int k0 = chunk * 16 + tig * 2;

        const float* r0 = A + (size_t)(m0 + g) * DIN + k0;
        const float* r1 = A + (size_t)(m0 + g + 8) * DIN + k0;
        float v[8] = { r0[0], r0[1], r1[0], r1[1], r0[8], r0[9], r1[8], r1[9] };

        float h[8], l[8];
#pragma unroll
        for (int i = 0; i < 8; ++i) {
            h[i] = __half2float(__float2half_rn(v[i]));
            l[i] = v[i] - h[i];
        }
        const size_t idx = ((size_t)mblk * NCHUNKS16 + chunk) * 256 + mtg * 32 + lane;
        Ahid[idx] = make_uint4(pack2(h[0], h[1]), pack2(h[2], h[3]),
                               pack2(h[4], h[5]), pack2(h[6], h[7]));
        Alod[idx] = make_uint4(pack2(l[0], l[1]), pack2(l[2], l[3]),
                               pack2(l[4], l[5]), pack2(l[6], l[7]));
    } else {
        const int q = (blockIdx.x - 4096) * blockDim.x + threadIdx.x;
        const int lane  = q & 31;
        const int p     = (q >> 5) & 7;
        const int chunk = (q >> 8) & (NCHUNKS16 - 1);
        const int nblk  = q >> 15;

        const int g = lane >> 2, tig = lane & 3;
        const int n_a = nblk * 128 + p * 16 + g;
        const int n_b = n_a + 8;
        const int k0 = chunk * 16 + tig * 2;

        const float* ra = W + (size_t)n_a * DIN + k0;
        const float* rb = W + (size_t)n_b * DIN + k0;
        float v[8] = { ra[0], ra[1], ra[8], ra[9], rb[0], rb[1], rb[8], rb[9] };

        float h[8], l[8];
#pragma unroll
        for (int i = 0; i < 8; ++i) {
            h[i] = __half2float(__float2half_rn(v[i]));
            l[i] = v[i] - h[i];
        }
        const size_t idx = ((size_t)nblk * NCHUNKS16 + chunk) * 256 + p * 32 + lane;
        Whid[idx] = make_uint4(pack2(h[0], h[1]), pack2(h[2], h[3]),
                               pack2(h[4], h[5]), pack2(h[6], h[7]));
        Wlod[idx] = make_uint4(pack2(l[0], l[1]), pack2(l[2], l[3]),
                               pack2(l[4], l[5]), pack2(l[6], l[7]));
    }
}

// ---------------------------------------------------------------------------
// fp16x3 GEMM, split-K=2, CTA tile 128x64, 8 warps (warp tile 64x16),
// 2 CTAs/SM (round-11 proven config — 260 us, rel_err 0):
//   Xz[m,n] = sum_{k in half z} A[m,k] * W[n,k]
// chunk32 mainloop, 3-stage cp.async pipeline.
// Windowed two-level accumulation (RZ chain bounded to K=128, RN flush).
// ---------------------------------------------------------------------------
__global__ __launch_bounds__(GEMM_THREADS, 2)
void gemm_fp16x3_kernel(const uint4* __restrict__ Ah, const uint4* __restrict__ Al,
                        const uint4* __restrict__ Bh, const uint4* __restrict__ Bl,
                        float* __restrict__ X0, float* __restrict__ X1)
{
    extern __shared__ __align__(16) char smem[];   // NSTAGES * STAGE_BYTES

    const int tid  = threadIdx.x;
    const int wid  = tid >> 5;
    const int lane = tid & 31;
    const int bx = blockIdx.x;          // N block (0..31), 64 cols each
    const int by = blockIdx.y;          // M block (0..31)
    const int bz = blockIdx.z;          // K half (0..1)
    const int wr = wid >> 2;            // warp row (0..1)  -> 64 M-rows
    const int wc = wid & 3;             // warp col (0..3)  -> 16 N-cols

    const uint32_t sbase = smem_u32(smem);
    const int c16base = bz * (NCHUNKS16 / SPLITK);   // 0 or 64
    const int nblk = bx >> 1;           // 128-wide B layout block
    const int nhalf = bx & 1;           // which 64-slice of it

    // one stage = one chunk32: A 1024 uint4, B 512 uint4. 6 cp.async/thread.
    auto issue = [&](int c32, int s) {
        const uint32_t sb = sbase + (uint32_t)s * STAGE_BYTES;
        const size_t a0 = ((size_t)by * NCHUNKS16 + c16base + c32 * 2) * 256;
        const size_t b0 = ((size_t)nblk * NCHUNKS16 + c16base + c32 * 2) * 256
                        + (size_t)nhalf * 128;
#pragma unroll
        for (int j = 0; j < 2; ++j) {
            const int t = tid + j * 256;
            cp16(sb + OFF_AH + t * 16, Ah + a0 + t);
            cp16(sb + OFF_AL + t * 16, Al + a0 + t);
        }
        {
            const int sub = tid >> 7;          // chunk16 index 0/1
            const int off = tid & 127;
            const size_t bsrc = b0 + (size_t)sub * 256 + off;
            cp16(sb + OFF_BH + tid * 16, Bh + bsrc);
            cp16(sb + OFF_BL + tid * 16, Bl + bsrc);
        }
        asm volatile("cp.async.commit_group;" ::: "memory");
    };

    float acc[4][2][4];    // master (RN adds only)
    float macc[4][2][4];   // HMMA window accumulator
#pragma unroll
    for (int i = 0; i < 4; ++i)
#pragma unroll
        for (int j = 0; j < 2; ++j)
#pragma unroll
            for (int r = 0; r < 4; ++r) acc[i][j][r] = 0.f;

    issue(0, 0);
    issue(1, 1);

    for (int i = 0; i < NC32_UNIT; ++i) {
        asm volatile("cp.async.wait_group 1;" ::: "memory");
        __syncthreads();

        if (i + 2 < NC32_UNIT) issue(i + 2, (i + 2) % NSTAGES);
        else asm volatile("cp.async.commit_group;" ::: "memory");

        const char* st = smem + (i % NSTAGES) * STAGE_BYTES;

        if ((i & (ACC_W32 - 1)) == 0) {
#pragma unroll
            for (int mt = 0; mt < 4; ++mt)
#pragma unroll
                for (int nt = 0; nt < 2; ++nt)
#pragma unroll
                    for (int r = 0; r < 4; ++r) macc[mt][nt][r] = 0.f;
        }

#pragma unroll
        for (int s = 0; s < 2; ++s) {            // two k16 sub-chunks
            // B fragments: one n-tile pair per warp (ntg = 2wc, 2wc+1)
            uint4 bhv = *(const uint4*)(st + OFF_BH + s * 2048 + (wc * 32 + lane) * 16);
            uint4 blv = *(const uint4*)(st + OFF_BL + s * 2048 + (wc * 32 + lane) * 16);
            const uint32_t* bhp = (const uint32_t*)&bhv;   // [0,1]=nt0, [2,3]=nt1
            const uint32_t* blp = (const uint32_t*)&blv;

            // A fragments: 4 m-tiles x 2 terms
            uint4 ahv[4], alv[4];
#pragma unroll
            for (int mt = 0; mt < 4; ++mt) {
                const int mtg = wr * 4 + mt;
                ahv[mt] = *(const uint4*)(st + OFF_AH + s * 4096 + (mtg * 32 + lane) * 16);
                alv[mt] = *(const uint4*)(st + OFF_AL + s * 4096 + (mtg * 32 + lane) * 16);
            }

#pragma unroll
            for (int mt = 0; mt < 4; ++mt) {
                const uint32_t* ah = (const uint32_t*)&ahv[mt];
                const uint32_t* al = (const uint32_t*)&alv[mt];
#pragma unroll
                for (int nt = 0; nt < 2; ++nt) {
                    mma16(macc[mt][nt], ah, bhp + 2 * nt);   // hi*hi
                    mma16(macc[mt][nt], ah, blp + 2 * nt);   // hi*lo
                    mma16(macc[mt][nt], al, bhp + 2 * nt);   // lo*hi
                }
            }
        }

        if ((i & (ACC_W32 - 1)) == (ACC_W32 - 1)) {
#pragma unroll
            for (int mt = 0; mt < 4; ++mt)
#pragma unroll
                for (int nt = 0; nt < 2; ++nt)
#pragma unroll
                    for (int r = 0; r < 4; ++r) acc[mt][nt][r] += macc[mt][nt][r];
        }
    }

    // epilogue: write partial to this unit's buffer
    float* X = (bz == 0) ? X0 : X1;
    const int r = lane >> 2, c2 = (lane & 3) * 2;
#pragma unroll
    for (int mt = 0; mt < 4; ++mt) {
#pragma unroll
        for (int nt = 0; nt < 2; ++nt) {
            const int m = by * 128 + wr * 64 + mt * 16 + r;
            const int n = bx * 64 + wc * 16 + nt * 8 + c2;
            *(float2*)&X[(size_t)m * DOUT + n] =
                make_float2(acc[mt][nt][0], acc[mt][nt][1]);
            *(float2*)&X[(size_t)(m + 8) * DOUT + n] =
                make_float2(acc[mt][nt][2], acc[mt][nt][3]);
        }
    }
}

// ---------------------------------------------------------------------------
// IF-neuron scan, float4 vectorized (4 outputs per thread):
//   x = X0 + X1 + bias; mem = mem*(1-spike) + x; spike = mem > 1
// ---------------------------------------------------------------------------
__global__ void if_scan_kernel(const float4* __restrict__ X0,
                               const float4* __restrict__ X1,
                               const float4* __restrict__ bias,
                               const float4* __restrict__ mem_init,
                               float4* __restrict__ out)
{
    const int idx = blockIdx.x * blockDim.x + threadIdx.x;   // 65536 threads
    const int o4 = idx & (DOUT / 4 - 1);   // 512 float4 per row
    const int b  = idx >> 9;

    const float4 bi = bias[o4];
    float4 mem = mem_init[idx];
    float4 spk = make_float4(0.f, 0.f, 0.f, 0.f);
    float4 acc = make_float4(0.f, 0.f, 0.f, 0.f);

#pragma unroll
    for (int t = 0; t < T_STEPS; ++t) {
        const size_t p = ((size_t)t * BATCH + b) * (DOUT / 4) + o4;
        const float4 x0 = X0[p];
        const float4 x1 = X1[p];
        mem.x = mem.x * (1.f - spk.x) + (x0.x + x1.x + bi.x);
        mem.y = mem.y * (1.f - spk.y) + (x0.y + x1.y + bi.y);
        mem.z = mem.z * (1.f - spk.z) + (x0.z + x1.z + bi.z);
        mem.w = mem.w * (1.f - spk.w) + (x0.w + x1.w + bi.w);
        spk.x = (mem.x > 1.f) ? 1.f : 0.f;
        spk.y = (mem.y > 1.f) ? 1.f : 0.f;
        spk.z = (mem.z > 1.f) ? 1.f : 0.f;
        spk.w = (mem.w > 1.f) ? 1.f : 0.f;
        acc.x += spk.x; acc.y += spk.y; acc.z += spk.z; acc.w += spk.w;
    }
    const float inv = 1.f / (float)T_STEPS;
    out[idx] = make_float4(acc.x * inv, acc.y * inv, acc.z * inv, acc.w * inv);
}

// ---------------------------------------------------------------------------
extern "C" void kernel_launch(void* const* d_in, const int* in_sizes, int n_in,
                              void* d_out, int out_size)
{
    const float* cur_inp  = (const float*)d_in[0];  // [T, B, DIN]
    const float* weight   = (const float*)d_in[1];  // [DOUT, DIN]
    const float* bias     = (const float*)d_in[2];  // [DOUT]
    const float* mem_init = (const float*)d_in[3];  // [B, DOUT]
    float* out = (float*)d_out;                     // [B, DOUT]

    float *X0, *X1;
    uint4 *Ah, *Al, *Wh, *Wl;
    cudaGetSymbolAddress((void**)&X0, g_X0);
    cudaGetSymbolAddress((void**)&X1, g_X1);
    cudaGetSymbolAddress((void**)&Ah, g_Ah);
    cudaGetSymbolAddress((void**)&Al, g_Al);
    cudaGetSymbolAddress((void**)&Wh, g_Wh);
    cudaGetSymbolAddress((void**)&Wl, g_Wl);

    cudaFuncSetAttribute(gemm_fp16x3_kernel,
                         cudaFuncAttributeMaxDynamicSharedMemorySize, SMEM_BYTES);

    // merged split + permute into mma fragment layout (fp16 hi/lo)
    split_kernel<<<6144, 256>>>(cur_inp, weight, Ah, Al, Wh, Wl);

    // fp16x3 tensor-core GEMM, split-K = 2, CTA tile 128x64, 2 CTAs/SM
    dim3 grid(DOUT / 64, M_ROWS / 128, SPLITK);   // (32, 32, 2)
    gemm_fp16x3_kernel<<<grid, GEMM_THREADS, SMEM_BYTES>>>(Ah, Al, Wh, Wl, X0, X1);

    // IF scan + split-K reduction (float4)
    if_scan_kernel<<<256, 256>>>((const float4*)X0, (const float4*)X1,
                                 (const float4*)bias, (const float4*)mem_init,
                                 (float4*)out);
}